// round 14
// baseline (speedup 1.0000x reference)
#include <cuda_runtime.h>
#include <cuda_bf16.h>
#include <cuda_fp16.h>
#include <math.h>
#include <stdint.h>

#define NT    4096
#define D     512
#define NHD   16
#define DH    32
#define DEPTH 3
#define DMLP  2048
#define GENES 250
#define GH    64
#define GW    64

// ---------------- PTX helpers ----------------
__device__ __forceinline__ uint32_t smem_u32(const void* p) {
    uint32_t a;
    asm("{ .reg .u64 t; cvta.to.shared.u64 t, %1; cvt.u32.u64 %0, t; }" : "=r"(a) : "l"(p));
    return a;
}
#define CP_ASYNC16(sa, ga) \
    asm volatile("cp.async.cg.shared.global [%0], [%1], 16;" :: "r"(sa), "l"(ga))
#define CP_COMMIT() asm volatile("cp.async.commit_group;")
#define CP_WAIT(n)  asm volatile("cp.async.wait_group %0;" :: "n"(n))

#define LDSM4(r0, r1, r2, r3, addr) \
    asm volatile("ldmatrix.sync.aligned.m8n8.x4.shared.b16 {%0,%1,%2,%3}, [%4];" \
        : "=r"(r0), "=r"(r1), "=r"(r2), "=r"(r3) : "r"(addr))
#define LDSM4T(r0, r1, r2, r3, addr) \
    asm volatile("ldmatrix.sync.aligned.m8n8.x4.trans.shared.b16 {%0,%1,%2,%3}, [%4];" \
        : "=r"(r0), "=r"(r1), "=r"(r2), "=r"(r3) : "r"(addr))

template <int F16>
__device__ __forceinline__ void mma_any(float* d, const uint32_t* a, const uint32_t* b) {
    if (F16)
        asm volatile("mma.sync.aligned.m16n8k16.row.col.f32.f16.f16.f32 "
            "{%0,%1,%2,%3}, {%4,%5,%6,%7}, {%8,%9}, {%0,%1,%2,%3};"
            : "+f"(d[0]), "+f"(d[1]), "+f"(d[2]), "+f"(d[3])
            : "r"(a[0]), "r"(a[1]), "r"(a[2]), "r"(a[3]), "r"(b[0]), "r"(b[1]));
    else
        asm volatile("mma.sync.aligned.m16n8k16.row.col.f32.bf16.bf16.f32 "
            "{%0,%1,%2,%3}, {%4,%5,%6,%7}, {%8,%9}, {%0,%1,%2,%3};"
            : "+f"(d[0]), "+f"(d[1]), "+f"(d[2]), "+f"(d[3])
            : "r"(a[0]), "r"(a[1]), "r"(a[2]), "r"(a[3]), "r"(b[0]), "r"(b[1]));
}
__device__ __forceinline__ void mma_bf16(float* d, const uint32_t* a, const uint32_t* b) {
    mma_any<0>(d, a, b);
}

#define PACKBF(d, lo, hi) \
    asm("cvt.rn.bf16x2.f32 %0, %1, %2;" : "=r"(d) : "f"(hi), "f"(lo))
#define PACKF16(d, lo, hi) \
    asm("cvt.rn.f16x2.f32 %0, %1, %2;" : "=r"(d) : "f"(hi), "f"(lo))
#define PRMT(d, a, b, s) \
    asm("prmt.b32 %0, %1, %2, %3;" : "=r"(d) : "r"(a), "r"(b), "n"(s))

__device__ __forceinline__ void hilo(float v, __nv_bfloat16& h, __nv_bfloat16& l) {
    h = __float2bfloat16(v);
    l = __float2bfloat16(v - __bfloat162float(h));
}
__device__ __forceinline__ void hilo16(float v, __half& h, __half& l) {
    h = __float2half_rn(v);
    l = __float2half_rn(v - __half2float(h));
}

// ---------------- device scratch ----------------
__device__ float g_x[NT * D];
__device__ float g_xb[NT * D];
__device__ int   g_idxg[GH * GW];
__device__ __nv_bfloat16 g_qkv_h[NT * 3 * D];
__device__ __half        g_xn16[NT * D];
__device__ __half        g_ao16[NT * D];
__device__ __half        g_h16[NT * DMLP];
__device__ __nv_bfloat16 g_xf_h[NT * D],  g_xf_l[NT * D];
__device__ __half        g_wq16h[DEPTH * 3 * D * D];
__device__ __half        g_w1_16h[DEPTH * DMLP * D], g_w1_16l[DEPTH * DMLP * D];
__device__ __half        g_w2_16h[DEPTH * D * DMLP], g_w2_16l[DEPTH * D * DMLP];
__device__ __half        g_wo16h[DEPTH * D * D],     g_wo16l[DEPTH * D * D];
__device__ __nv_bfloat16 g_wp_h[GENES * D],          g_wp_l[GENES * D];

// ---- one merged weight-conversion kernel ----
#define N_WQKV (DEPTH * 3 * D * D)
#define N_W1   (DEPTH * DMLP * D)
#define N_W2   (DEPTH * D * DMLP)
#define N_WO   (DEPTH * D * D)
#define N_WP   (GENES * D)
#define N_CVT  (N_WQKV + N_W1 + N_W2 + N_WO + N_WP)

__global__ void cvt_all(const float* __restrict__ wqkv, const float* __restrict__ w1,
                        const float* __restrict__ w2, const float* __restrict__ wo,
                        const float* __restrict__ wp) {
    int j = blockIdx.x * blockDim.x + threadIdx.x;
    if (j < N_WQKV) { g_wq16h[j] = __float2half_rn(wqkv[j]); return; }
    j -= N_WQKV;
    if (j < N_W1) {
        __half h, l; hilo16(w1[j], h, l); g_w1_16h[j] = h; g_w1_16l[j] = l; return;
    }
    j -= N_W1;
    if (j < N_W2) {
        __half h, l; hilo16(w2[j], h, l); g_w2_16h[j] = h; g_w2_16l[j] = l; return;
    }
    j -= N_W2;
    if (j < N_WO) {
        __half h, l; hilo16(wo[j], h, l); g_wo16h[j] = h; g_wo16l[j] = l; return;
    }
    j -= N_WO;
    if (j < N_WP) {
        __nv_bfloat16 h, l; hilo(wp[j], h, l); g_wp_h[j] = h; g_wp_l[j] = l;
    }
}

// ---- inverse coords map ----
__global__ void build_idx(const int* __restrict__ coords) {
    int n = blockIdx.x * blockDim.x + threadIdx.x;
    if (n < NT) g_idxg[coords[2 * n] * GW + coords[2 * n + 1]] = n;
}

// ---------------- LayerNorm -> fp16 single ---------------------------------
__global__ void ln_f16(const float* __restrict__ in, __half* __restrict__ oh,
                       const float* __restrict__ gam, const float* __restrict__ bet) {
    int row = blockIdx.x, t = threadIdx.x;
    float4 v = ((const float4*)(in + (size_t)row * D))[t];
    float s = v.x + v.y + v.z + v.w;
    float ss = v.x * v.x + v.y * v.y + v.z * v.z + v.w * v.w;
#pragma unroll
    for (int off = 16; off; off >>= 1) {
        s  += __shfl_xor_sync(0xffffffffu, s, off);
        ss += __shfl_xor_sync(0xffffffffu, ss, off);
    }
    __shared__ float sb[4], ssb[4];
    int w = t >> 5, lane = t & 31;
    if (lane == 0) { sb[w] = s; ssb[w] = ss; }
    __syncthreads();
    s = sb[0] + sb[1] + sb[2] + sb[3];
    ss = ssb[0] + ssb[1] + ssb[2] + ssb[3];
    float mean = s * (1.0f / D);
    float inv = rsqrtf(ss * (1.0f / D) - mean * mean + 1e-5f);
    float4 g4 = ((const float4*)gam)[t];
    float4 b4 = ((const float4*)bet)[t];
    float o0 = (v.x - mean) * inv * g4.x + b4.x;
    float o1 = (v.y - mean) * inv * g4.y + b4.y;
    float o2 = (v.z - mean) * inv * g4.z + b4.z;
    float o3 = (v.w - mean) * inv * g4.w + b4.w;
    uint2 pk;
    PACKF16(pk.x, o0, o1);
    PACKF16(pk.y, o2, o3);
    *(uint2*)(oh + (size_t)row * D + t * 4) = pk;
}

// ---------------- LayerNorm -> bf16 hi/lo + fp32 (final LN) ----------------
__global__ void ln_bf(const float* __restrict__ in, float* __restrict__ out32,
                      __nv_bfloat16* __restrict__ oh, __nv_bfloat16* __restrict__ ol,
                      const float* __restrict__ gam, const float* __restrict__ bet) {
    int row = blockIdx.x, t = threadIdx.x;
    float4 v = ((const float4*)(in + (size_t)row * D))[t];
    float s = v.x + v.y + v.z + v.w;
    float ss = v.x * v.x + v.y * v.y + v.z * v.z + v.w * v.w;
#pragma unroll
    for (int off = 16; off; off >>= 1) {
        s  += __shfl_xor_sync(0xffffffffu, s, off);
        ss += __shfl_xor_sync(0xffffffffu, ss, off);
    }
    __shared__ float sb[4], ssb[4];
    int w = t >> 5, lane = t & 31;
    if (lane == 0) { sb[w] = s; ssb[w] = ss; }
    __syncthreads();
    s = sb[0] + sb[1] + sb[2] + sb[3];
    ss = ssb[0] + ssb[1] + ssb[2] + ssb[3];
    float mean = s * (1.0f / D);
    float inv = rsqrtf(ss * (1.0f / D) - mean * mean + 1e-5f);
    float4 g4 = ((const float4*)gam)[t];
    float4 b4 = ((const float4*)bet)[t];
    float o0 = (v.x - mean) * inv * g4.x + b4.x;
    float o1 = (v.y - mean) * inv * g4.y + b4.y;
    float o2 = (v.z - mean) * inv * g4.z + b4.z;
    float o3 = (v.w - mean) * inv * g4.w + b4.w;
    size_t base = (size_t)row * D + t * 4;
    __nv_bfloat16 h0, l0, h1, l1, h2, l2, h3, l3;
    hilo(o0, h0, l0); hilo(o1, h1, l1); hilo(o2, h2, l2); hilo(o3, h3, l3);
    __nv_bfloat162 p;
    p.x = h0; p.y = h1; *(__nv_bfloat162*)(oh + base) = p;
    p.x = h2; p.y = h3; *(__nv_bfloat162*)(oh + base + 2) = p;
    p.x = l0; p.y = l1; *(__nv_bfloat162*)(ol + base) = p;
    p.x = l2; p.y = l3; *(__nv_bfloat162*)(ol + base + 2) = p;
    float4 o; o.x = o0; o.y = o1; o.z = o2; o.w = o3;
    ((float4*)(out32 + (size_t)row * D))[t] = o;
}

// ---------------- 16-bit hi/lo GEMM via mma.sync ----------------------------
// Compacted smem stage: only the tiles each TERMS variant uses.
//   TERMS=1: [A, Wh]           stage = 2 tiles (20 KB)
//   TERMS=2: [A, Wh, Wl]       stage = 3 tiles (30 KB)
//   TERMS=3: [A, Al, Wh, Wl]   stage = 4 tiles (40 KB)
#define TPITCH 80
#define TILE_B (128 * TPITCH)
#define NTILES(T)  ((T) + 1)
#define STG(T)     (NTILES(T) * TILE_B)
#define GDYN(T)    (2 * STG(T))
#define WH_OFF(T)  (((T) == 3 ? 2 : 1) * TILE_B)

template <int TERMS>
__device__ __forceinline__ void stage_load(
    uint32_t sbase, const uint16_t* Ah, const uint16_t* Al,
    const uint16_t* Wh, const uint16_t* Wl,
    int mrow, int ncol, int OUT, int K, int kt, int tid) {
#pragma unroll
    for (int i = 0; i < 2; i++) {
        int chunk = tid + i * 256;
        int r = chunk >> 2, c16 = chunk & 3;
        uint32_t so = (uint32_t)(r * TPITCH + c16 * 16);
        size_t aoff = (size_t)(mrow + r) * K + kt + c16 * 8;
        int wr = ncol + r; if (wr >= OUT) wr = OUT - 1;
        size_t woff = (size_t)wr * K + kt + c16 * 8;
        CP_ASYNC16(sbase + so,                  (const char*)(Ah + aoff));
        if (TERMS == 3)
            CP_ASYNC16(sbase + TILE_B + so,     (const char*)(Al + aoff));
        CP_ASYNC16(sbase + WH_OFF(TERMS) + so,  (const char*)(Wh + woff));
        if (TERMS >= 2)
            CP_ASYNC16(sbase + WH_OFF(TERMS) + TILE_B + so, (const char*)(Wl + woff));
    }
}

// MODE 0: out32=v+bias ; 2: out32=res+v+bias ; 4: out16=pack(v+bias) ;
// 5: out16=pack(gelu(v+bias))
template <int MODE, int TERMS, int F16, int OUTF16>
__global__ void __launch_bounds__(256) gemm_mma(
    const uint16_t* __restrict__ Ah, const uint16_t* __restrict__ Al,
    const uint16_t* __restrict__ Wh, const uint16_t* __restrict__ Wl,
    const float* __restrict__ bias, const float* __restrict__ res32,
    float* __restrict__ out32, uint16_t* __restrict__ out16, int OUT, int K) {
    extern __shared__ char dyn_raw[];
    const int tid = threadIdx.x, wid = tid >> 5, lane = tid & 31;
    const int mrow = blockIdx.y * 128, ncol = blockIdx.x * 128;
    const int warp_m = wid & 1, warp_n = wid >> 1;
    const int m_off = warp_m * 64, n_off = warp_n * 32;
    const int NIT = K >> 5;
    uint32_t smem0 = smem_u32(dyn_raw);

    float acc[4][4][4];
#pragma unroll
    for (int a = 0; a < 4; a++)
#pragma unroll
        for (int b = 0; b < 4; b++)
#pragma unroll
            for (int c = 0; c < 4; c++) acc[a][b][c] = 0.f;

    const uint32_t a_lm = (uint32_t)((m_off + (lane & 15)) * TPITCH + (lane & 16));
    const int bl = lane & 7, bg = (lane >> 3) & 3;
    const uint32_t b_lm = (uint32_t)((n_off + ((bg >> 1) << 3) + bl) * TPITCH + ((bg & 1) << 4));

    stage_load<TERMS>(smem0, Ah, Al, Wh, Wl, mrow, ncol, OUT, K, 0, tid);
    CP_COMMIT();

    for (int it = 0; it < NIT; it++) {
        if (it + 1 < NIT) {
            stage_load<TERMS>(smem0 + ((it + 1) & 1) * STG(TERMS), Ah, Al, Wh, Wl,
                              mrow, ncol, OUT, K, (it + 1) * 32, tid);
            CP_COMMIT();
            CP_WAIT(1);
        } else {
            CP_WAIT(0);
        }
        __syncthreads();
        uint32_t sb = smem0 + (it & 1) * STG(TERMS);
#pragma unroll
        for (int ks = 0; ks < 2; ks++) {
            uint32_t kb = (uint32_t)(ks * 32);
            uint32_t ah[4][4], al[4][4], bh[4][2], bl2[4][2];
#pragma unroll
            for (int mt = 0; mt < 4; mt++) {
                uint32_t ad = sb + a_lm + mt * (16 * TPITCH) + kb;
                LDSM4(ah[mt][0], ah[mt][1], ah[mt][2], ah[mt][3], ad);
                if (TERMS == 3)
                    LDSM4(al[mt][0], al[mt][1], al[mt][2], al[mt][3], ad + TILE_B);
            }
#pragma unroll
            for (int np = 0; np < 2; np++) {
                uint32_t bd = sb + WH_OFF(TERMS) + b_lm + np * (16 * TPITCH) + kb;
                LDSM4(bh[2 * np][0], bh[2 * np][1], bh[2 * np + 1][0], bh[2 * np + 1][1], bd);
                if (TERMS >= 2)
                    LDSM4(bl2[2 * np][0], bl2[2 * np][1], bl2[2 * np + 1][0], bl2[2 * np + 1][1], bd + TILE_B);
            }
#pragma unroll
            for (int mt = 0; mt < 4; mt++)
#pragma unroll
                for (int nt = 0; nt < 4; nt++) {
                    mma_any<F16>(acc[mt][nt], ah[mt], bh[nt]);
                    if (TERMS >= 2)
                        mma_any<F16>(acc[mt][nt], ah[mt], bl2[nt]);
                    if (TERMS == 3)
                        mma_any<F16>(acc[mt][nt], al[mt], bh[nt]);
                }
        }
        __syncthreads();
    }

    const int r0 = lane >> 2, cp = (lane & 3) * 2;
#pragma unroll
    for (int mt = 0; mt < 4; mt++)
#pragma unroll
        for (int nt = 0; nt < 4; nt++) {
            int col = ncol + n_off + nt * 8 + cp;
            if (col >= OUT) continue;
            float bx = bias[col], by = bias[col + 1];
#pragma unroll
            for (int half = 0; half < 2; half++) {
                int row = mrow + m_off + mt * 16 + r0 + half * 8;
                float vx = acc[mt][nt][2 * half] + bx;
                float vy = acc[mt][nt][2 * half + 1] + by;
                size_t idx = (size_t)row * OUT + col;
                if (MODE == 0) {
                    *(float2*)(out32 + idx) = make_float2(vx, vy);
                } else if (MODE == 4 || MODE == 5) {
                    if (MODE == 5) {
                        vx = 0.5f * vx * (1.0f + erff(vx * 0.70710678118654752f));
                        vy = 0.5f * vy * (1.0f + erff(vy * 0.70710678118654752f));
                    }
                    uint32_t hp;
                    if (OUTF16) PACKF16(hp, vx, vy);
                    else        PACKBF(hp, vx, vy);
                    *(uint32_t*)(out16 + idx) = hp;
                } else {
                    float2 o = *(const float2*)(res32 + idx);
                    o.x += vx; o.y += vy;
                    *(float2*)(out32 + idx) = o;
                }
            }
        }
}

// ---------------- flash attention, bf16, max-free + Schraudolph exp ---------
#define AP 80
#define KVT (64 * AP)
#define ASTG (2 * KVT)
#define ATTN_DYN (2 * ASTG)
#define SC_A 261.13688f
#define MAGICF 12582912.0f
#define EXPC 1064987000u

__global__ void __launch_bounds__(128) attn_tc() {
    extern __shared__ __align__(16) char smem[];
    const int tid = threadIdx.x, wid = tid >> 5, lane = tid & 31;
    const int h = blockIdx.x, qb = blockIdx.y * 64;
    const uint32_t s0 = smem_u32(smem);

#pragma unroll
    for (int i = 0; i < 2; i++) {
        int idx = tid + i * 128;
        int r = idx >> 2, c = idx & 3;
        CP_ASYNC16(s0 + r * AP + c * 16,
                   g_qkv_h + (size_t)(qb + r) * 1536 + h * 32 + c * 8);
    }
    CP_COMMIT(); CP_WAIT(0); __syncthreads();
    uint32_t qh[2][4];
    {
        uint32_t alm = s0 + (wid * 16 + (lane & 15)) * AP + (lane & 16);
        LDSM4(qh[0][0], qh[0][1], qh[0][2], qh[0][3], alm);
        LDSM4(qh[1][0], qh[1][1], qh[1][2], qh[1][3], alm + 32);
    }
    __syncthreads();

    const int bl = lane & 7, bg = (lane >> 3) & 3;
    const uint32_t koff = (uint32_t)((((bg >> 1) * 8) + bl) * AP + ((bg & 1) * 16));
    const uint32_t voff = (uint32_t)(((((lane >> 3) & 1) * 8) + (lane & 7)) * AP + (((lane >> 4) & 1) * 16));

    float O[4][4];
#pragma unroll
    for (int a = 0; a < 4; a++)
#pragma unroll
        for (int b = 0; b < 4; b++) O[a][b] = 0.f;
    float lsum0 = 0.f, lsum1 = 0.f;

    {
#pragma unroll
        for (int i = 0; i < 4; i++) {
            int idx = tid + i * 128;
            int tile = idx >> 8, rem = idx & 255, r = rem >> 2, c = rem & 3;
            int col = (tile ? 1024 : 512) + h * 32;
            CP_ASYNC16(s0 + tile * KVT + r * AP + c * 16,
                       g_qkv_h + (size_t)r * 1536 + col + c * 8);
        }
        CP_COMMIT();
    }

    for (int t = 0; t < NT / 64; t++) {
        if (t + 1 < NT / 64) {
            int kb = (t + 1) * 64;
            uint32_t st = s0 + ((t + 1) & 1) * ASTG;
#pragma unroll
            for (int i = 0; i < 4; i++) {
                int idx = tid + i * 128;
                int tile = idx >> 8, rem = idx & 255, r = rem >> 2, c = rem & 3;
                int col = (tile ? 1024 : 512) + h * 32;
                CP_ASYNC16(st + tile * KVT + r * AP + c * 16,
                           g_qkv_h + (size_t)(kb + r) * 1536 + col + c * 8);
            }
            CP_COMMIT(); CP_WAIT(1);
        } else {
            CP_WAIT(0);
        }
        __syncthreads();
        uint32_t sb = s0 + (t & 1) * ASTG;

        float S[8][4];
#pragma unroll
        for (int a = 0; a < 8; a++)
#pragma unroll
            for (int b = 0; b < 4; b++) S[a][b] = 0.f;
#pragma unroll
        for (int ks = 0; ks < 2; ks++) {
            uint32_t kh[8][2];
#pragma unroll
            for (int np = 0; np < 4; np++) {
                uint32_t ad = sb + np * (16 * AP) + koff + ks * 32;
                LDSM4(kh[2 * np][0], kh[2 * np][1], kh[2 * np + 1][0], kh[2 * np + 1][1], ad);
            }
#pragma unroll
            for (int nt = 0; nt < 8; nt++)
                mma_bf16(S[nt], qh[ks], kh[nt]);
        }

        uint32_t ph01[8], ph23[8];
#pragma unroll
        for (int nt = 0; nt < 8; nt++) {
            uint32_t i0 = __float_as_uint(fmaf(S[nt][0], SC_A, MAGICF)) * 8192u + EXPC;
            uint32_t i1 = __float_as_uint(fmaf(S[nt][1], SC_A, MAGICF)) * 8192u + EXPC;
            uint32_t i2 = __float_as_uint(fmaf(S[nt][2], SC_A, MAGICF)) * 8192u + EXPC;
            uint32_t i3 = __float_as_uint(fmaf(S[nt][3], SC_A, MAGICF)) * 8192u + EXPC;
            lsum0 += __uint_as_float(i0) + __uint_as_float(i1);
            lsum1 += __uint_as_float(i2) + __uint_as_float(i3);
            PRMT(ph01[nt], i0, i1, 0x7632);
            PRMT(ph23[nt], i2, i3, 0x7632);
        }

#pragma unroll
        for (int s = 0; s < 4; s++) {
            uint32_t aH[4] = { ph01[2 * s], ph23[2 * s], ph01[2 * s + 1], ph23[2 * s + 1] };
            uint32_t vh[4][2];
#pragma unroll
            for (int d2 = 0; d2 < 2; d2++) {
                uint32_t ad = sb + KVT + s * (16 * AP) + voff + d2 * 32;
                LDSM4T(vh[2 * d2][0], vh[2 * d2][1], vh[2 * d2 + 1][0], vh[2 * d2 + 1][1], ad);
            }
#pragma unroll
            for (int nt = 0; nt < 4; nt++)
                mma_bf16(O[nt], aH, vh[nt]);
        }
        __syncthreads();
    }

    lsum0 += __shfl_xor_sync(0xffffffffu, lsum0, 1);
    lsum0 += __shfl_xor_sync(0xffffffffu, lsum0, 2);
    lsum1 += __shfl_xor_sync(0xffffffffu, lsum1, 1);
    lsum1 += __shfl_xor_sync(0xffffffffu, lsum1, 2);
    float i0 = 1.f / lsum0, i1 = 1.f / lsum1;
    int r0 = qb + wid * 16 + (lane >> 2), r1 = r0 + 8;
    int colb = h * 32 + (lane & 3) * 2;
#pragma unroll
    for (int nt = 0; nt < 4; nt++) {
        int col = colb + nt * 8;
        uint32_t hp;
        PACKF16(hp, O[nt][0] * i0, O[nt][1] * i0);
        *(uint32_t*)(g_ao16 + (size_t)r0 * D + col) = hp;
        PACKF16(hp, O[nt][2] * i1, O[nt][3] * i1);
        *(uint32_t*)(g_ao16 + (size_t)r1 * D + col) = hp;
    }
}

// ---------------- fused conv+gather via inverse index grid ------------------
__global__ void convgather_kernel(const float* __restrict__ xin,
                                  float* __restrict__ xout,
                                  const int* __restrict__ coords,
                                  const float* __restrict__ ck,
                                  const float* __restrict__ cb) {
    int idx = blockIdx.x * blockDim.x + threadIdx.x;
    int n = idx >> 9, d = idx & (D - 1);
    int r = coords[2 * n], c = coords[2 * n + 1];
    float acc = cb[d];
#pragma unroll
    for (int kh = 0; kh < 3; kh++) {
        int rr = r + kh - 1;
        if ((unsigned)rr >= GH) continue;
#pragma unroll
        for (int kw = 0; kw < 3; kw++) {
            int cc = c + kw - 1;
            if ((unsigned)cc >= GW) continue;
            int nn = g_idxg[rr * GW + cc];
            acc += ck[d * 9 + kh * 3 + kw] * xin[(size_t)nn * D + d];
        }
    }
    xout[idx] = xin[idx] + acc;
}

// ---------------- host ----------------
extern "C" void kernel_launch(void* const* d_in, const int* in_sizes, int n_in,
                              void* d_out, int out_size) {
    const float* gf     = (const float*)d_in[0];
    const int*   coords = (const int*)d_in[1];
    int wi = (n_in >= 22) ? 4 : 2;
    const float* ln1_g = (const float*)d_in[wi + 0];
    const float* ln1_b = (const float*)d_in[wi + 1];
    const float* wqkv  = (const float*)d_in[wi + 2];
    const float* bqkv  = (const float*)d_in[wi + 3];
    const float* wo    = (const float*)d_in[wi + 4];
    const float* bo    = (const float*)d_in[wi + 5];
    const float* ln2_g = (const float*)d_in[wi + 6];
    const float* ln2_b = (const float*)d_in[wi + 7];
    const float* w1    = (const float*)d_in[wi + 8];
    const float* b1    = (const float*)d_in[wi + 9];
    const float* w2    = (const float*)d_in[wi + 10];
    const float* b2    = (const float*)d_in[wi + 11];
    const float* ck    = (const float*)d_in[wi + 12];
    const float* cb    = (const float*)d_in[wi + 13];
    const float* lnf_g = (const float*)d_in[wi + 14];
    const float* lnf_b = (const float*)d_in[wi + 15];
    const float* wp    = (const float*)d_in[wi + 16];
    const float* bp    = (const float*)d_in[wi + 17];

    float* out_x    = (float*)d_out;
    float* out_pred = out_x + (size_t)NT * D;

    static float *pxa = nullptr, *pxb;
    static uint16_t *pqh, *pxn16, *pao16, *ph16, *pxfh, *pxfl;
    static uint16_t *pWq16h, *pW1h, *pW1l, *pW2h, *pW2l, *pWoh, *pWol, *pWph, *pWpl;
    if (!pxa) {
        cudaGetSymbolAddress((void**)&pxa, g_x);
        cudaGetSymbolAddress((void**)&pxb, g_xb);
        cudaGetSymbolAddress((void**)&pqh, g_qkv_h);
        cudaGetSymbolAddress((void**)&pxn16, g_xn16);
        cudaGetSymbolAddress((void**)&pao16, g_ao16);
        cudaGetSymbolAddress((void**)&ph16, g_h16);
        cudaGetSymbolAddress((void**)&pxfh, g_xf_h);  cudaGetSymbolAddress((void**)&pxfl, g_xf_l);
        cudaGetSymbolAddress((void**)&pWq16h, g_wq16h);
        cudaGetSymbolAddress((void**)&pW1h, g_w1_16h);  cudaGetSymbolAddress((void**)&pW1l, g_w1_16l);
        cudaGetSymbolAddress((void**)&pW2h, g_w2_16h);  cudaGetSymbolAddress((void**)&pW2l, g_w2_16l);
        cudaGetSymbolAddress((void**)&pWoh, g_wo16h);   cudaGetSymbolAddress((void**)&pWol, g_wo16l);
        cudaGetSymbolAddress((void**)&pWph, g_wp_h);    cudaGetSymbolAddress((void**)&pWpl, g_wp_l);
        cudaFuncSetAttribute((const void*)gemm_mma<0, 3, 0, 0>, cudaFuncAttributeMaxDynamicSharedMemorySize, GDYN(3));
        cudaFuncSetAttribute((const void*)gemm_mma<4, 1, 1, 0>, cudaFuncAttributeMaxDynamicSharedMemorySize, GDYN(1));
        cudaFuncSetAttribute((const void*)gemm_mma<5, 2, 1, 1>, cudaFuncAttributeMaxDynamicSharedMemorySize, GDYN(2));
        cudaFuncSetAttribute((const void*)gemm_mma<2, 2, 1, 0>, cudaFuncAttributeMaxDynamicSharedMemorySize, GDYN(2));
        cudaFuncSetAttribute((const void*)attn_tc, cudaFuncAttributeMaxDynamicSharedMemorySize, ATTN_DYN);
    }

    cudaMemcpyAsync(pxa, gf, (size_t)NT * D * sizeof(float), cudaMemcpyDeviceToDevice);

    cvt_all<<<(N_CVT + 255) / 256, 256>>>(wqkv, w1, w2, wo, wp);
    build_idx<<<NT / 256, 256>>>(coords);

    float* cur = pxa;
    float* nxt = pxb;
    for (int i = 0; i < DEPTH; i++) {
        ln_f16<<<NT, 128>>>(cur, (__half*)pxn16, ln1_g + i * D, ln1_b + i * D);
        gemm_mma<4, 1, 1, 0><<<dim3(12, 32), 256, GDYN(1)>>>(
            pxn16, nullptr, pWq16h + (size_t)i * 3 * D * D, nullptr,
            bqkv + i * 3 * D, nullptr, nullptr, pqh, 3 * D, D);
        attn_tc<<<dim3(NHD, NT / 64), 128, ATTN_DYN>>>();
        gemm_mma<2, 2, 1, 0><<<dim3(4, 32), 256, GDYN(2)>>>(
            pao16, nullptr, pWoh + (size_t)i * D * D, pWol + (size_t)i * D * D,
            bo + i * D, cur, cur, nullptr, D, D);
        ln_f16<<<NT, 128>>>(cur, (__half*)pxn16, ln2_g + i * D, ln2_b + i * D);
        gemm_mma<5, 2, 1, 1><<<dim3(16, 32), 256, GDYN(2)>>>(
            pxn16, nullptr, pW1h + (size_t)i * DMLP * D, pW1l + (size_t)i * DMLP * D,
            b1 + i * DMLP, nullptr, nullptr, ph16, DMLP, D);
        gemm_mma<2, 2, 1, 0><<<dim3(4, 32), 256, GDYN(2)>>>(
            ph16, nullptr, pW2h + (size_t)i * D * DMLP, pW2l + (size_t)i * D * DMLP,
            b2 + i * D, cur, cur, nullptr, D, DMLP);
        convgather_kernel<<<NT * D / 256, 256>>>(cur, nxt, coords,
                                                 ck + (size_t)i * D * 9, cb + i * D);
        float* tmp = cur; cur = nxt; nxt = tmp;
    }
    ln_bf<<<NT, 128>>>(cur, out_x, (__nv_bfloat16*)pxfh, (__nv_bfloat16*)pxfl, lnf_g, lnf_b);
    gemm_mma<0, 3, 0, 0><<<dim3(2, 32), 256, GDYN(3)>>>(
        pxfh, pxfl, pWph, pWpl, bp, nullptr, out_pred, nullptr, GENES, D);
}

// round 15
// speedup vs baseline: 1.5384x; 1.5384x over previous
#include <cuda_runtime.h>
#include <cuda_bf16.h>
#include <cuda_fp16.h>
#include <math.h>
#include <stdint.h>

#define NT    4096
#define D     512
#define NHD   16
#define DH    32
#define DEPTH 3
#define DMLP  2048
#define GENES 250
#define GH    64
#define GW    64

// ---------------- PTX helpers ----------------
__device__ __forceinline__ uint32_t smem_u32(const void* p) {
    uint32_t a;
    asm("{ .reg .u64 t; cvta.to.shared.u64 t, %1; cvt.u32.u64 %0, t; }" : "=r"(a) : "l"(p));
    return a;
}
#define CP_ASYNC16(sa, ga) \
    asm volatile("cp.async.cg.shared.global [%0], [%1], 16;" :: "r"(sa), "l"(ga))
#define CP_COMMIT() asm volatile("cp.async.commit_group;")
#define CP_WAIT(n)  asm volatile("cp.async.wait_group %0;" :: "n"(n))

#define LDSM4(r0, r1, r2, r3, addr) \
    asm volatile("ldmatrix.sync.aligned.m8n8.x4.shared.b16 {%0,%1,%2,%3}, [%4];" \
        : "=r"(r0), "=r"(r1), "=r"(r2), "=r"(r3) : "r"(addr))
#define LDSM4T(r0, r1, r2, r3, addr) \
    asm volatile("ldmatrix.sync.aligned.m8n8.x4.trans.shared.b16 {%0,%1,%2,%3}, [%4];" \
        : "=r"(r0), "=r"(r1), "=r"(r2), "=r"(r3) : "r"(addr))

template <int F16>
__device__ __forceinline__ void mma_any(float* d, const uint32_t* a, const uint32_t* b) {
    if (F16)
        asm volatile("mma.sync.aligned.m16n8k16.row.col.f32.f16.f16.f32 "
            "{%0,%1,%2,%3}, {%4,%5,%6,%7}, {%8,%9}, {%0,%1,%2,%3};"
            : "+f"(d[0]), "+f"(d[1]), "+f"(d[2]), "+f"(d[3])
            : "r"(a[0]), "r"(a[1]), "r"(a[2]), "r"(a[3]), "r"(b[0]), "r"(b[1]));
    else
        asm volatile("mma.sync.aligned.m16n8k16.row.col.f32.bf16.bf16.f32 "
            "{%0,%1,%2,%3}, {%4,%5,%6,%7}, {%8,%9}, {%0,%1,%2,%3};"
            : "+f"(d[0]), "+f"(d[1]), "+f"(d[2]), "+f"(d[3])
            : "r"(a[0]), "r"(a[1]), "r"(a[2]), "r"(a[3]), "r"(b[0]), "r"(b[1]));
}
__device__ __forceinline__ void mma_bf16(float* d, const uint32_t* a, const uint32_t* b) {
    mma_any<0>(d, a, b);
}

#define PACKBF(d, lo, hi) \
    asm("cvt.rn.bf16x2.f32 %0, %1, %2;" : "=r"(d) : "f"(hi), "f"(lo))
#define PACKF16(d, lo, hi) \
    asm("cvt.rn.f16x2.f32 %0, %1, %2;" : "=r"(d) : "f"(hi), "f"(lo))
#define PRMT(d, a, b, s) \
    asm("prmt.b32 %0, %1, %2, %3;" : "=r"(d) : "r"(a), "r"(b), "n"(s))

__device__ __forceinline__ void hilo(float v, __nv_bfloat16& h, __nv_bfloat16& l) {
    h = __float2bfloat16(v);
    l = __float2bfloat16(v - __bfloat162float(h));
}
__device__ __forceinline__ void hilo16(float v, __half& h, __half& l) {
    h = __float2half_rn(v);
    l = __float2half_rn(v - __half2float(h));
}

// ---------------- device scratch ----------------
__device__ float g_x[NT * D];
__device__ float g_xb[NT * D];
__device__ int   g_idxg[GH * GW];
__device__ __nv_bfloat16 g_qkv_h[NT * 3 * D];
__device__ __half        g_xn16[NT * D];
__device__ __half        g_ao16[NT * D];
__device__ __half        g_h16[NT * DMLP];
__device__ __nv_bfloat16 g_xf_h[NT * D],  g_xf_l[NT * D];
__device__ __half        g_wq16h[DEPTH * 3 * D * D];
__device__ __half        g_w1_16h[DEPTH * DMLP * D], g_w1_16l[DEPTH * DMLP * D];
__device__ __half        g_w2_16h[DEPTH * D * DMLP], g_w2_16l[DEPTH * D * DMLP];
__device__ __half        g_wo16h[DEPTH * D * D],     g_wo16l[DEPTH * D * D];
__device__ __nv_bfloat16 g_wp_h[GENES * D],          g_wp_l[GENES * D];

// ---- one merged weight-conversion kernel ----
#define N_WQKV (DEPTH * 3 * D * D)
#define N_W1   (DEPTH * DMLP * D)
#define N_W2   (DEPTH * D * DMLP)
#define N_WO   (DEPTH * D * D)
#define N_WP   (GENES * D)
#define N_CVT  (N_WQKV + N_W1 + N_W2 + N_WO + N_WP)

__global__ void cvt_all(const float* __restrict__ wqkv, const float* __restrict__ w1,
                        const float* __restrict__ w2, const float* __restrict__ wo,
                        const float* __restrict__ wp) {
    int j = blockIdx.x * blockDim.x + threadIdx.x;
    if (j < N_WQKV) { g_wq16h[j] = __float2half_rn(wqkv[j]); return; }
    j -= N_WQKV;
    if (j < N_W1) {
        __half h, l; hilo16(w1[j], h, l); g_w1_16h[j] = h; g_w1_16l[j] = l; return;
    }
    j -= N_W1;
    if (j < N_W2) {
        __half h, l; hilo16(w2[j], h, l); g_w2_16h[j] = h; g_w2_16l[j] = l; return;
    }
    j -= N_W2;
    if (j < N_WO) {
        __half h, l; hilo16(wo[j], h, l); g_wo16h[j] = h; g_wo16l[j] = l; return;
    }
    j -= N_WO;
    if (j < N_WP) {
        __nv_bfloat16 h, l; hilo(wp[j], h, l); g_wp_h[j] = h; g_wp_l[j] = l;
    }
}

// ---- inverse coords map ----
__global__ void build_idx(const int* __restrict__ coords) {
    int n = blockIdx.x * blockDim.x + threadIdx.x;
    if (n < NT) g_idxg[coords[2 * n] * GW + coords[2 * n + 1]] = n;
}

// ---------------- LayerNorm -> fp16 single ---------------------------------
__global__ void ln_f16(const float* __restrict__ in, __half* __restrict__ oh,
                       const float* __restrict__ gam, const float* __restrict__ bet) {
    int row = blockIdx.x, t = threadIdx.x;
    float4 v = ((const float4*)(in + (size_t)row * D))[t];
    float s = v.x + v.y + v.z + v.w;
    float ss = v.x * v.x + v.y * v.y + v.z * v.z + v.w * v.w;
#pragma unroll
    for (int off = 16; off; off >>= 1) {
        s  += __shfl_xor_sync(0xffffffffu, s, off);
        ss += __shfl_xor_sync(0xffffffffu, ss, off);
    }
    __shared__ float sb[4], ssb[4];
    int w = t >> 5, lane = t & 31;
    if (lane == 0) { sb[w] = s; ssb[w] = ss; }
    __syncthreads();
    s = sb[0] + sb[1] + sb[2] + sb[3];
    ss = ssb[0] + ssb[1] + ssb[2] + ssb[3];
    float mean = s * (1.0f / D);
    float inv = rsqrtf(ss * (1.0f / D) - mean * mean + 1e-5f);
    float4 g4 = ((const float4*)gam)[t];
    float4 b4 = ((const float4*)bet)[t];
    float o0 = (v.x - mean) * inv * g4.x + b4.x;
    float o1 = (v.y - mean) * inv * g4.y + b4.y;
    float o2 = (v.z - mean) * inv * g4.z + b4.z;
    float o3 = (v.w - mean) * inv * g4.w + b4.w;
    uint2 pk;
    PACKF16(pk.x, o0, o1);
    PACKF16(pk.y, o2, o3);
    *(uint2*)(oh + (size_t)row * D + t * 4) = pk;
}

// ---------------- LayerNorm -> bf16 hi/lo + fp32 (final LN) ----------------
__global__ void ln_bf(const float* __restrict__ in, float* __restrict__ out32,
                      __nv_bfloat16* __restrict__ oh, __nv_bfloat16* __restrict__ ol,
                      const float* __restrict__ gam, const float* __restrict__ bet) {
    int row = blockIdx.x, t = threadIdx.x;
    float4 v = ((const float4*)(in + (size_t)row * D))[t];
    float s = v.x + v.y + v.z + v.w;
    float ss = v.x * v.x + v.y * v.y + v.z * v.z + v.w * v.w;
#pragma unroll
    for (int off = 16; off; off >>= 1) {
        s  += __shfl_xor_sync(0xffffffffu, s, off);
        ss += __shfl_xor_sync(0xffffffffu, ss, off);
    }
    __shared__ float sb[4], ssb[4];
    int w = t >> 5, lane = t & 31;
    if (lane == 0) { sb[w] = s; ssb[w] = ss; }
    __syncthreads();
    s = sb[0] + sb[1] + sb[2] + sb[3];
    ss = ssb[0] + ssb[1] + ssb[2] + ssb[3];
    float mean = s * (1.0f / D);
    float inv = rsqrtf(ss * (1.0f / D) - mean * mean + 1e-5f);
    float4 g4 = ((const float4*)gam)[t];
    float4 b4 = ((const float4*)bet)[t];
    float o0 = (v.x - mean) * inv * g4.x + b4.x;
    float o1 = (v.y - mean) * inv * g4.y + b4.y;
    float o2 = (v.z - mean) * inv * g4.z + b4.z;
    float o3 = (v.w - mean) * inv * g4.w + b4.w;
    size_t base = (size_t)row * D + t * 4;
    __nv_bfloat16 h0, l0, h1, l1, h2, l2, h3, l3;
    hilo(o0, h0, l0); hilo(o1, h1, l1); hilo(o2, h2, l2); hilo(o3, h3, l3);
    __nv_bfloat162 p;
    p.x = h0; p.y = h1; *(__nv_bfloat162*)(oh + base) = p;
    p.x = h2; p.y = h3; *(__nv_bfloat162*)(oh + base + 2) = p;
    p.x = l0; p.y = l1; *(__nv_bfloat162*)(ol + base) = p;
    p.x = l2; p.y = l3; *(__nv_bfloat162*)(ol + base + 2) = p;
    float4 o; o.x = o0; o.y = o1; o.z = o2; o.w = o3;
    ((float4*)(out32 + (size_t)row * D))[t] = o;
}

// ---------------- 16-bit hi/lo GEMM, 3-stage cp.async pipeline --------------
// Compact stages: TERMS=1 [A,Wh] 20KB ; TERMS=2 [A,Wh,Wl] 30KB ; TERMS=3 [A,Al,Wh,Wl] 40KB.
// 3 stages: wait on stage it with it+1 in flight, prefetch it+2 -> one full
// iteration of MMA work covers the load latency.
#define TPITCH 80
#define TILE_B (128 * TPITCH)
#define NTILES(T)  ((T) + 1)
#define STG(T)     (NTILES(T) * TILE_B)
#define GDYN(T)    (3 * STG(T))
#define WH_OFF(T)  (((T) == 3 ? 2 : 1) * TILE_B)

template <int TERMS>
__device__ __forceinline__ void stage_load(
    uint32_t sbase, const uint16_t* Ah, const uint16_t* Al,
    const uint16_t* Wh, const uint16_t* Wl,
    int mrow, int ncol, int OUT, int K, int kt, int tid) {
#pragma unroll
    for (int i = 0; i < 2; i++) {
        int chunk = tid + i * 256;
        int r = chunk >> 2, c16 = chunk & 3;
        uint32_t so = (uint32_t)(r * TPITCH + c16 * 16);
        size_t aoff = (size_t)(mrow + r) * K + kt + c16 * 8;
        int wr = ncol + r; if (wr >= OUT) wr = OUT - 1;
        size_t woff = (size_t)wr * K + kt + c16 * 8;
        CP_ASYNC16(sbase + so,                  (const char*)(Ah + aoff));
        if (TERMS == 3)
            CP_ASYNC16(sbase + TILE_B + so,     (const char*)(Al + aoff));
        CP_ASYNC16(sbase + WH_OFF(TERMS) + so,  (const char*)(Wh + woff));
        if (TERMS >= 2)
            CP_ASYNC16(sbase + WH_OFF(TERMS) + TILE_B + so, (const char*)(Wl + woff));
    }
}

// MODE 0: out32=v+bias ; 2: out32=res+v+bias ; 4: out16=pack(v+bias) ;
// 5: out16=pack(gelu(v+bias))
template <int MODE, int TERMS, int F16, int OUTF16>
__global__ void __launch_bounds__(256) gemm_mma(
    const uint16_t* __restrict__ Ah, const uint16_t* __restrict__ Al,
    const uint16_t* __restrict__ Wh, const uint16_t* __restrict__ Wl,
    const float* __restrict__ bias, const float* __restrict__ res32,
    float* __restrict__ out32, uint16_t* __restrict__ out16, int OUT, int K) {
    extern __shared__ char dyn_raw[];
    const int tid = threadIdx.x, wid = tid >> 5, lane = tid & 31;
    const int mrow = blockIdx.y * 128, ncol = blockIdx.x * 128;
    const int warp_m = wid & 1, warp_n = wid >> 1;
    const int m_off = warp_m * 64, n_off = warp_n * 32;
    const int NIT = K >> 5;
    uint32_t smem0 = smem_u32(dyn_raw);
    uint32_t sbuf0 = smem0, sbuf1 = smem0 + STG(TERMS), sbuf2 = smem0 + 2 * STG(TERMS);

    float acc[4][4][4];
#pragma unroll
    for (int a = 0; a < 4; a++)
#pragma unroll
        for (int b = 0; b < 4; b++)
#pragma unroll
            for (int c = 0; c < 4; c++) acc[a][b][c] = 0.f;

    const uint32_t a_lm = (uint32_t)((m_off + (lane & 15)) * TPITCH + (lane & 16));
    const int bl = lane & 7, bg = (lane >> 3) & 3;
    const uint32_t b_lm = (uint32_t)((n_off + ((bg >> 1) << 3) + bl) * TPITCH + ((bg & 1) << 4));

    stage_load<TERMS>(sbuf0, Ah, Al, Wh, Wl, mrow, ncol, OUT, K, 0, tid);
    CP_COMMIT();
    stage_load<TERMS>(sbuf1, Ah, Al, Wh, Wl, mrow, ncol, OUT, K, 32, tid);
    CP_COMMIT();

    int cs = 0, pf = 2;
    for (int it = 0; it < NIT; it++) {
        if (it + 1 < NIT) { CP_WAIT(1); } else { CP_WAIT(0); }
        __syncthreads();
        if (it + 2 < NIT) {
            uint32_t dst = (pf == 0) ? sbuf0 : (pf == 1) ? sbuf1 : sbuf2;
            stage_load<TERMS>(dst, Ah, Al, Wh, Wl, mrow, ncol, OUT, K, (it + 2) * 32, tid);
            CP_COMMIT();
        }
        uint32_t sb = (cs == 0) ? sbuf0 : (cs == 1) ? sbuf1 : sbuf2;
#pragma unroll
        for (int ks = 0; ks < 2; ks++) {
            uint32_t kb = (uint32_t)(ks * 32);
            uint32_t ah[4][4], al[4][4], bh[4][2], bl2[4][2];
#pragma unroll
            for (int mt = 0; mt < 4; mt++) {
                uint32_t ad = sb + a_lm + mt * (16 * TPITCH) + kb;
                LDSM4(ah[mt][0], ah[mt][1], ah[mt][2], ah[mt][3], ad);
                if (TERMS == 3)
                    LDSM4(al[mt][0], al[mt][1], al[mt][2], al[mt][3], ad + TILE_B);
            }
#pragma unroll
            for (int np = 0; np < 2; np++) {
                uint32_t bd = sb + WH_OFF(TERMS) + b_lm + np * (16 * TPITCH) + kb;
                LDSM4(bh[2 * np][0], bh[2 * np][1], bh[2 * np + 1][0], bh[2 * np + 1][1], bd);
                if (TERMS >= 2)
                    LDSM4(bl2[2 * np][0], bl2[2 * np][1], bl2[2 * np + 1][0], bl2[2 * np + 1][1], bd + TILE_B);
            }
#pragma unroll
            for (int mt = 0; mt < 4; mt++)
#pragma unroll
                for (int nt = 0; nt < 4; nt++) {
                    mma_any<F16>(acc[mt][nt], ah[mt], bh[nt]);
                    if (TERMS >= 2)
                        mma_any<F16>(acc[mt][nt], ah[mt], bl2[nt]);
                    if (TERMS == 3)
                        mma_any<F16>(acc[mt][nt], al[mt], bh[nt]);
                }
        }
        __syncthreads();
        cs = (cs == 2) ? 0 : cs + 1;
        pf = (pf == 2) ? 0 : pf + 1;
    }

    const int r0 = lane >> 2, cp = (lane & 3) * 2;
#pragma unroll
    for (int mt = 0; mt < 4; mt++)
#pragma unroll
        for (int nt = 0; nt < 4; nt++) {
            int col = ncol + n_off + nt * 8 + cp;
            if (col >= OUT) continue;
            float bx = bias[col], by = bias[col + 1];
#pragma unroll
            for (int half = 0; half < 2; half++) {
                int row = mrow + m_off + mt * 16 + r0 + half * 8;
                float vx = acc[mt][nt][2 * half] + bx;
                float vy = acc[mt][nt][2 * half + 1] + by;
                size_t idx = (size_t)row * OUT + col;
                if (MODE == 0) {
                    *(float2*)(out32 + idx) = make_float2(vx, vy);
                } else if (MODE == 4 || MODE == 5) {
                    if (MODE == 5) {
                        vx = 0.5f * vx * (1.0f + erff(vx * 0.70710678118654752f));
                        vy = 0.5f * vy * (1.0f + erff(vy * 0.70710678118654752f));
                    }
                    uint32_t hp;
                    if (OUTF16) PACKF16(hp, vx, vy);
                    else        PACKBF(hp, vx, vy);
                    *(uint32_t*)(out16 + idx) = hp;
                } else {
                    float2 o = *(const float2*)(res32 + idx);
                    o.x += vx; o.y += vy;
                    *(float2*)(out32 + idx) = o;
                }
            }
        }
}

// ---------------- flash attention, bf16, max-free + Schraudolph exp ---------
#define AP 80
#define KVT (64 * AP)
#define ASTG (2 * KVT)
#define ATTN_DYN (2 * ASTG)
#define SC_A 261.13688f
#define MAGICF 12582912.0f
#define EXPC 1064987000u

__global__ void __launch_bounds__(128) attn_tc() {
    extern __shared__ __align__(16) char smem[];
    const int tid = threadIdx.x, wid = tid >> 5, lane = tid & 31;
    const int h = blockIdx.x, qb = blockIdx.y * 64;
    const uint32_t s0 = smem_u32(smem);

#pragma unroll
    for (int i = 0; i < 2; i++) {
        int idx = tid + i * 128;
        int r = idx >> 2, c = idx & 3;
        CP_ASYNC16(s0 + r * AP + c * 16,
                   g_qkv_h + (size_t)(qb + r) * 1536 + h * 32 + c * 8);
    }
    CP_COMMIT(); CP_WAIT(0); __syncthreads();
    uint32_t qh[2][4];
    {
        uint32_t alm = s0 + (wid * 16 + (lane & 15)) * AP + (lane & 16);
        LDSM4(qh[0][0], qh[0][1], qh[0][2], qh[0][3], alm);
        LDSM4(qh[1][0], qh[1][1], qh[1][2], qh[1][3], alm + 32);
    }
    __syncthreads();

    const int bl = lane & 7, bg = (lane >> 3) & 3;
    const uint32_t koff = (uint32_t)((((bg >> 1) * 8) + bl) * AP + ((bg & 1) * 16));
    const uint32_t voff = (uint32_t)(((((lane >> 3) & 1) * 8) + (lane & 7)) * AP + (((lane >> 4) & 1) * 16));

    float O[4][4];
#pragma unroll
    for (int a = 0; a < 4; a++)
#pragma unroll
        for (int b = 0; b < 4; b++) O[a][b] = 0.f;
    float lsum0 = 0.f, lsum1 = 0.f;

    {
#pragma unroll
        for (int i = 0; i < 4; i++) {
            int idx = tid + i * 128;
            int tile = idx >> 8, rem = idx & 255, r = rem >> 2, c = rem & 3;
            int col = (tile ? 1024 : 512) + h * 32;
            CP_ASYNC16(s0 + tile * KVT + r * AP + c * 16,
                       g_qkv_h + (size_t)r * 1536 + col + c * 8);
        }
        CP_COMMIT();
    }

    for (int t = 0; t < NT / 64; t++) {
        if (t + 1 < NT / 64) {
            int kb = (t + 1) * 64;
            uint32_t st = s0 + ((t + 1) & 1) * ASTG;
#pragma unroll
            for (int i = 0; i < 4; i++) {
                int idx = tid + i * 128;
                int tile = idx >> 8, rem = idx & 255, r = rem >> 2, c = rem & 3;
                int col = (tile ? 1024 : 512) + h * 32;
                CP_ASYNC16(st + tile * KVT + r * AP + c * 16,
                           g_qkv_h + (size_t)(kb + r) * 1536 + col + c * 8);
            }
            CP_COMMIT(); CP_WAIT(1);
        } else {
            CP_WAIT(0);
        }
        __syncthreads();
        uint32_t sb = s0 + (t & 1) * ASTG;

        float S[8][4];
#pragma unroll
        for (int a = 0; a < 8; a++)
#pragma unroll
            for (int b = 0; b < 4; b++) S[a][b] = 0.f;
#pragma unroll
        for (int ks = 0; ks < 2; ks++) {
            uint32_t kh[8][2];
#pragma unroll
            for (int np = 0; np < 4; np++) {
                uint32_t ad = sb + np * (16 * AP) + koff + ks * 32;
                LDSM4(kh[2 * np][0], kh[2 * np][1], kh[2 * np + 1][0], kh[2 * np + 1][1], ad);
            }
#pragma unroll
            for (int nt = 0; nt < 8; nt++)
                mma_bf16(S[nt], qh[ks], kh[nt]);
        }

        uint32_t ph01[8], ph23[8];
#pragma unroll
        for (int nt = 0; nt < 8; nt++) {
            uint32_t i0 = __float_as_uint(fmaf(S[nt][0], SC_A, MAGICF)) * 8192u + EXPC;
            uint32_t i1 = __float_as_uint(fmaf(S[nt][1], SC_A, MAGICF)) * 8192u + EXPC;
            uint32_t i2 = __float_as_uint(fmaf(S[nt][2], SC_A, MAGICF)) * 8192u + EXPC;
            uint32_t i3 = __float_as_uint(fmaf(S[nt][3], SC_A, MAGICF)) * 8192u + EXPC;
            lsum0 += __uint_as_float(i0) + __uint_as_float(i1);
            lsum1 += __uint_as_float(i2) + __uint_as_float(i3);
            PRMT(ph01[nt], i0, i1, 0x7632);
            PRMT(ph23[nt], i2, i3, 0x7632);
        }

#pragma unroll
        for (int s = 0; s < 4; s++) {
            uint32_t aH[4] = { ph01[2 * s], ph23[2 * s], ph01[2 * s + 1], ph23[2 * s + 1] };
            uint32_t vh[4][2];
#pragma unroll
            for (int d2 = 0; d2 < 2; d2++) {
                uint32_t ad = sb + KVT + s * (16 * AP) + voff + d2 * 32;
                LDSM4T(vh[2 * d2][0], vh[2 * d2][1], vh[2 * d2 + 1][0], vh[2 * d2 + 1][1], ad);
            }
#pragma unroll
            for (int nt = 0; nt < 4; nt++)
                mma_bf16(O[nt], aH, vh[nt]);
        }
        __syncthreads();
    }

    lsum0 += __shfl_xor_sync(0xffffffffu, lsum0, 1);
    lsum0 += __shfl_xor_sync(0xffffffffu, lsum0, 2);
    lsum1 += __shfl_xor_sync(0xffffffffu, lsum1, 1);
    lsum1 += __shfl_xor_sync(0xffffffffu, lsum1, 2);
    float i0 = 1.f / lsum0, i1 = 1.f / lsum1;
    int r0 = qb + wid * 16 + (lane >> 2), r1 = r0 + 8;
    int colb = h * 32 + (lane & 3) * 2;
#pragma unroll
    for (int nt = 0; nt < 4; nt++) {
        int col = colb + nt * 8;
        uint32_t hp;
        PACKF16(hp, O[nt][0] * i0, O[nt][1] * i0);
        *(uint32_t*)(g_ao16 + (size_t)r0 * D + col) = hp;
        PACKF16(hp, O[nt][2] * i1, O[nt][3] * i1);
        *(uint32_t*)(g_ao16 + (size_t)r1 * D + col) = hp;
    }
}

// ---------------- fused conv+gather via inverse index grid ------------------
__global__ void convgather_kernel(const float* __restrict__ xin,
                                  float* __restrict__ xout,
                                  const int* __restrict__ coords,
                                  const float* __restrict__ ck,
                                  const float* __restrict__ cb) {
    int idx = blockIdx.x * blockDim.x + threadIdx.x;
    int n = idx >> 9, d = idx & (D - 1);
    int r = coords[2 * n], c = coords[2 * n + 1];
    float acc = cb[d];
#pragma unroll
    for (int kh = 0; kh < 3; kh++) {
        int rr = r + kh - 1;
        if ((unsigned)rr >= GH) continue;
#pragma unroll
        for (int kw = 0; kw < 3; kw++) {
            int cc = c + kw - 1;
            if ((unsigned)cc >= GW) continue;
            int nn = g_idxg[rr * GW + cc];
            acc += ck[d * 9 + kh * 3 + kw] * xin[(size_t)nn * D + d];
        }
    }
    xout[idx] = xin[idx] + acc;
}

// ---------------- host ----------------
extern "C" void kernel_launch(void* const* d_in, const int* in_sizes, int n_in,
                              void* d_out, int out_size) {
    const float* gf     = (const float*)d_in[0];
    const int*   coords = (const int*)d_in[1];
    int wi = (n_in >= 22) ? 4 : 2;
    const float* ln1_g = (const float*)d_in[wi + 0];
    const float* ln1_b = (const float*)d_in[wi + 1];
    const float* wqkv  = (const float*)d_in[wi + 2];
    const float* bqkv  = (const float*)d_in[wi + 3];
    const float* wo    = (const float*)d_in[wi + 4];
    const float* bo    = (const float*)d_in[wi + 5];
    const float* ln2_g = (const float*)d_in[wi + 6];
    const float* ln2_b = (const float*)d_in[wi + 7];
    const float* w1    = (const float*)d_in[wi + 8];
    const float* b1    = (const float*)d_in[wi + 9];
    const float* w2    = (const float*)d_in[wi + 10];
    const float* b2    = (const float*)d_in[wi + 11];
    const float* ck    = (const float*)d_in[wi + 12];
    const float* cb    = (const float*)d_in[wi + 13];
    const float* lnf_g = (const float*)d_in[wi + 14];
    const float* lnf_b = (const float*)d_in[wi + 15];
    const float* wp    = (const float*)d_in[wi + 16];
    const float* bp    = (const float*)d_in[wi + 17];

    float* out_x    = (float*)d_out;
    float* out_pred = out_x + (size_t)NT * D;

    static float *pxa = nullptr, *pxb;
    static uint16_t *pqh, *pxn16, *pao16, *ph16, *pxfh, *pxfl;
    static uint16_t *pWq16h, *pW1h, *pW1l, *pW2h, *pW2l, *pWoh, *pWol, *pWph, *pWpl;
    if (!pxa) {
        cudaGetSymbolAddress((void**)&pxa, g_x);
        cudaGetSymbolAddress((void**)&pxb, g_xb);
        cudaGetSymbolAddress((void**)&pqh, g_qkv_h);
        cudaGetSymbolAddress((void**)&pxn16, g_xn16);
        cudaGetSymbolAddress((void**)&pao16, g_ao16);
        cudaGetSymbolAddress((void**)&ph16, g_h16);
        cudaGetSymbolAddress((void**)&pxfh, g_xf_h);  cudaGetSymbolAddress((void**)&pxfl, g_xf_l);
        cudaGetSymbolAddress((void**)&pWq16h, g_wq16h);
        cudaGetSymbolAddress((void**)&pW1h, g_w1_16h);  cudaGetSymbolAddress((void**)&pW1l, g_w1_16l);
        cudaGetSymbolAddress((void**)&pW2h, g_w2_16h);  cudaGetSymbolAddress((void**)&pW2l, g_w2_16l);
        cudaGetSymbolAddress((void**)&pWoh, g_wo16h);   cudaGetSymbolAddress((void**)&pWol, g_wo16l);
        cudaGetSymbolAddress((void**)&pWph, g_wp_h);    cudaGetSymbolAddress((void**)&pWpl, g_wp_l);
        cudaFuncSetAttribute((const void*)gemm_mma<0, 3, 0, 0>, cudaFuncAttributeMaxDynamicSharedMemorySize, GDYN(3));
        cudaFuncSetAttribute((const void*)gemm_mma<4, 1, 1, 0>, cudaFuncAttributeMaxDynamicSharedMemorySize, GDYN(1));
        cudaFuncSetAttribute((const void*)gemm_mma<5, 2, 1, 1>, cudaFuncAttributeMaxDynamicSharedMemorySize, GDYN(2));
        cudaFuncSetAttribute((const void*)gemm_mma<2, 2, 1, 0>, cudaFuncAttributeMaxDynamicSharedMemorySize, GDYN(2));
        cudaFuncSetAttribute((const void*)attn_tc, cudaFuncAttributeMaxDynamicSharedMemorySize, ATTN_DYN);
    }

    cudaMemcpyAsync(pxa, gf, (size_t)NT * D * sizeof(float), cudaMemcpyDeviceToDevice);

    cvt_all<<<(N_CVT + 255) / 256, 256>>>(wqkv, w1, w2, wo, wp);
    build_idx<<<NT / 256, 256>>>(coords);

    float* cur = pxa;
    float* nxt = pxb;
    for (int i = 0; i < DEPTH; i++) {
        ln_f16<<<NT, 128>>>(cur, (__half*)pxn16, ln1_g + i * D, ln1_b + i * D);
        gemm_mma<4, 1, 1, 0><<<dim3(12, 32), 256, GDYN(1)>>>(
            pxn16, nullptr, pWq16h + (size_t)i * 3 * D * D, nullptr,
            bqkv + i * 3 * D, nullptr, nullptr, pqh, 3 * D, D);
        attn_tc<<<dim3(NHD, NT / 64), 128, ATTN_DYN>>>();
        gemm_mma<2, 2, 1, 0><<<dim3(4, 32), 256, GDYN(2)>>>(
            pao16, nullptr, pWoh + (size_t)i * D * D, pWol + (size_t)i * D * D,
            bo + i * D, cur, cur, nullptr, D, D);
        ln_f16<<<NT, 128>>>(cur, (__half*)pxn16, ln2_g + i * D, ln2_b + i * D);
        gemm_mma<5, 2, 1, 1><<<dim3(16, 32), 256, GDYN(2)>>>(
            pxn16, nullptr, pW1h + (size_t)i * DMLP * D, pW1l + (size_t)i * DMLP * D,
            b1 + i * DMLP, nullptr, nullptr, ph16, DMLP, D);
        gemm_mma<2, 2, 1, 0><<<dim3(4, 32), 256, GDYN(2)>>>(
            ph16, nullptr, pW2h + (size_t)i * D * DMLP, pW2l + (size_t)i * D * DMLP,
            b2 + i * D, cur, cur, nullptr, D, DMLP);
        convgather_kernel<<<NT * D / 256, 256>>>(cur, nxt, coords,
                                                 ck + (size_t)i * D * 9, cb + i * D);
        float* tmp = cur; cur = nxt; nxt = tmp;
    }
    ln_bf<<<NT, 128>>>(cur, out_x, (__nv_bfloat16*)pxfh, (__nv_bfloat16*)pxfl, lnf_g, lnf_b);
    gemm_mma<0, 3, 0, 0><<<dim3(2, 32), 256, GDYN(3)>>>(
        pxfh, pxfl, pWph, pWpl, bp, nullptr, out_pred, nullptr, GENES, D);
}